// round 3
// baseline (speedup 1.0000x reference)
#include <cuda_runtime.h>

#define N     4096
#define KDIM  512
#define OUTD  512
#define H     8
#define D     64
#define ALPHA 0.2f
#define EPSLN 1e-5f

// ---------------- scratch (__device__ globals; no allocs allowed) -----------
__device__ __align__(16) float  g_Wh[N * OUTD];      // 8 MB
__device__ float4 g_src[H * N];                      // {s_src, e^{s}, e^{0.2s}, 0}
__device__ float4 g_dst[H * N];                      // {s_dst, e^{s}, e^{0.2s}, 0}
__device__ __align__(16) float  g_pnum[2 * N * OUTD];// 16 MB (j-half partial numerators)
__device__ float  g_pZ[2 * N * H];                   // partial denominators
__device__ __align__(16) float  g_hp[N * OUTD];      // 8 MB  (h_prime pre-norm)
__device__ float  g_csum[OUTD];
__device__ float  g_csq[OUTD];

// ---- packed fp32x2 FMA (Blackwell FFMA2; unreachable from plain C++) -------
__device__ __forceinline__ unsigned long long ffma2(unsigned long long a,
                                                    unsigned long long b,
                                                    unsigned long long c) {
    unsigned long long d;
    asm("fma.rn.f32x2 %0, %1, %2, %3;" : "=l"(d) : "l"(a), "l"(b), "l"(c));
    return d;
}
__device__ __forceinline__ unsigned long long pack2(float lo, float hi) {
    unsigned long long r;
    asm("mov.b64 %0, {%1, %2};" : "=l"(r) : "f"(lo), "f"(hi));
    return r;
}

// ---------------- 1) Wh = x @ W^T  (fp32 tiled GEMM) ------------------------
__global__ __launch_bounds__(256) void k_gemm(const float* __restrict__ x,
                                              const float* __restrict__ W) {
    __shared__ __align__(16) float xs[16][68];   // [k][i], padded
    __shared__ __align__(16) float ws[16][68];   // [k][o], padded
    int tx = threadIdx.x & 15, ty = threadIdx.x >> 4;
    int o0 = blockIdx.x * 64, i0 = blockIdx.y * 64;
    float acc[4][4] = {};
    for (int k0 = 0; k0 < KDIM; k0 += 16) {
        __syncthreads();
#pragma unroll
        for (int m = 0; m < 4; m++) {
            int idx = m * 256 + threadIdx.x;
            int r = idx >> 4, c = idx & 15;
            xs[c][r] = x[(size_t)(i0 + r) * KDIM + k0 + c];
            ws[c][r] = W[(size_t)(o0 + r) * KDIM + k0 + c];
        }
        __syncthreads();
#pragma unroll
        for (int k = 0; k < 16; k++) {
            float4 av = *(const float4*)&xs[k][ty * 4];
            float4 bv = *(const float4*)&ws[k][tx * 4];
            float aa[4] = {av.x, av.y, av.z, av.w};
            float bb[4] = {bv.x, bv.y, bv.z, bv.w};
#pragma unroll
            for (int a = 0; a < 4; a++)
#pragma unroll
                for (int b = 0; b < 4; b++)
                    acc[a][b] = fmaf(aa[a], bb[b], acc[a][b]);
        }
    }
#pragma unroll
    for (int a = 0; a < 4; a++) {
        float4 v = make_float4(acc[a][0], acc[a][1], acc[a][2], acc[a][3]);
        *(float4*)&g_Wh[(size_t)(i0 + ty * 4 + a) * OUTD + o0 + tx * 4] = v;
    }
}

// ---------------- 2) per-(node, head) scores + separable exponentials -------
__global__ __launch_bounds__(256) void k_scores(const float* __restrict__ a) {
    int gt = blockIdx.x * 256 + threadIdx.x;   // 0 .. N*H-1
    int j = gt >> 3, h = gt & 7;
    const float4* row = (const float4*)&g_Wh[(size_t)j * OUTD + h * D];
    const float4* a4  = (const float4*)a;      // a[0:64]=a_src, a[64:128]=a_dst
    float ss = 0.f, sd = 0.f;
#pragma unroll
    for (int q = 0; q < 16; q++) {
        float4 w  = row[q];
        float4 as = a4[q];
        float4 ad = a4[16 + q];
        ss += w.x * as.x + w.y * as.y + w.z * as.z + w.w * as.w;
        sd += w.x * ad.x + w.y * ad.y + w.z * ad.z + w.w * ad.w;
    }
    g_src[h * N + j] = make_float4(ss, expf(ss), expf(ALPHA * ss), 0.f);
    g_dst[h * N + j] = make_float4(sd, expf(sd), expf(ALPHA * sd), 0.f);
}

// ---------------- 3) fused masked softmax-aggregation -----------------------
// Block: 32 rows (lanes) x 8 heads (warps). Each thread accumulates all D=64
// channels for its (i, h) as 32 packed f32x2 registers; inner loop issues 32
// FFMA2 (= 64 fp32 FMAs) per neighbor. j staged in smem chunks of 16.
// grid.y in {0,1} splits the j-range so >=256 blocks keep the chip busy.
__global__ __launch_bounds__(256, 2) void k_attn(const int* __restrict__ adj) {
    __shared__ __align__(16) float4 wh_s[16 * 128];  // [j][c], 32 KB, uniform reads
    __shared__ int   adj_s[32 * 17];                 // [i][j], pad 17 -> conflict-free
    __shared__ __align__(16) float4 sp_s[16 * 9];    // [j][h], pad 9

    int lane = threadIdx.x & 31, h = threadIdx.x >> 5;
    int i0 = blockIdx.x * 32, i = i0 + lane;

    float4 dp = g_dst[h * N + i];
    float sdi = dp.x, EpD = dp.y, EnD = dp.z;

    unsigned long long acc[32];
#pragma unroll
    for (int k = 0; k < 32; k++) acc[k] = 0ull;
    float Z = 0.f;

    int jbase = blockIdx.y * (N / 2);
    for (int jc = jbase; jc < jbase + N / 2; jc += 16) {
        __syncthreads();
#pragma unroll
        for (int m = 0; m < 8; m++) {
            int idx = m * 256 + threadIdx.x;
            int j = idx >> 7, c = idx & 127;
            wh_s[idx] = *(const float4*)&g_Wh[(size_t)(jc + j) * OUTD + c * 4];
        }
#pragma unroll
        for (int m = 0; m < 2; m++) {
            int idx = m * 256 + threadIdx.x;
            int r = idx >> 4, c = idx & 15;
            adj_s[r * 17 + c] = adj[(size_t)(i0 + r) * N + jc + c];
        }
        if (threadIdx.x < 128) {
            int jj = threadIdx.x & 15, hh = threadIdx.x >> 4;
            sp_s[jj * 9 + hh] = g_src[hh * N + jc + jj];
        }
        __syncthreads();

#pragma unroll 4
        for (int jj = 0; jj < 16; jj++) {
            float4 sp = sp_s[jj * 9 + h];
            float s = sdi + sp.x;
            float w = (s > 0.f) ? (EpD * sp.y) : (EnD * sp.z);
            if (adj_s[lane * 17 + jj] == 0) w = 0.f;
            Z += w;
            unsigned long long w2 = pack2(w, w);
            // 64 floats = 32 x 64-bit packed lanes, warp-uniform smem broadcast
            const unsigned long long* wp =
                (const unsigned long long*)&wh_s[jj * 128 + h * 16];
#pragma unroll
            for (int k = 0; k < 32; k++)
                acc[k] = ffma2(w2, wp[k], acc[k]);
        }
    }

    int half = blockIdx.y;
    unsigned long long* po = (unsigned long long*)
        &g_pnum[(size_t)half * N * OUTD + (size_t)i * OUTD + h * D];
#pragma unroll
    for (int k = 0; k < 32; k++) po[k] = acc[k];
    g_pZ[half * N * H + i * H + h] = Z;
}

// ---------------- 4) combine halves + column stats ---------------------------
__global__ void k_zero() {
    int t = threadIdx.x;
    if (t < OUTD) { g_csum[t] = 0.f; g_csq[t] = 0.f; }
}

__global__ __launch_bounds__(256) void k_combine() {
    int r0 = blockIdx.x * 32;
    int c0 = threadIdx.x, c1 = threadIdx.x + 256;
    int h0 = c0 >> 6, h1 = c1 >> 6;
    float s0 = 0.f, q0 = 0.f, s1 = 0.f, q1 = 0.f;
    for (int r = 0; r < 32; r++) {
        int i = r0 + r;
        float Za = g_pZ[i * H + h0] + g_pZ[N * H + i * H + h0];
        float Zb = g_pZ[i * H + h1] + g_pZ[N * H + i * H + h1];
        float v0 = (g_pnum[(size_t)i * OUTD + c0] + g_pnum[(size_t)N * OUTD + (size_t)i * OUTD + c0]) / Za;
        float v1 = (g_pnum[(size_t)i * OUTD + c1] + g_pnum[(size_t)N * OUTD + (size_t)i * OUTD + c1]) / Zb;
        g_hp[(size_t)i * OUTD + c0] = v0;
        g_hp[(size_t)i * OUTD + c1] = v1;
        s0 += v0; q0 += v0 * v0;
        s1 += v1; q1 += v1 * v1;
    }
    atomicAdd(&g_csum[c0], s0); atomicAdd(&g_csq[c0], q0);
    atomicAdd(&g_csum[c1], s1); atomicAdd(&g_csq[c1], q1);
}

// ---------------- 5) feature-norm (axis 0) + ReLU ---------------------------
__global__ __launch_bounds__(256) void k_norm(const float* __restrict__ gamma,
                                              const float* __restrict__ beta,
                                              float* __restrict__ out) {
    int idx = blockIdx.x * 256 + threadIdx.x;
    int c = idx & (OUTD - 1);
    float mean = g_csum[c] * (1.f / N);
    float var  = g_csq[c] * (1.f / N) - mean * mean;
    float v = g_hp[idx];
    float o = gamma[c] * (v - mean) * rsqrtf(var + EPSLN) + beta[c];
    out[idx] = fmaxf(o, 0.f);
}

// ---------------- launch -----------------------------------------------------
extern "C" void kernel_launch(void* const* d_in, const int* in_sizes, int n_in,
                              void* d_out, int out_size) {
    const float* x     = (const float*)d_in[0];
    const int*   adj   = (const int*)d_in[1];
    const float* W     = (const float*)d_in[2];
    const float* a     = (const float*)d_in[3];
    const float* gamma = (const float*)d_in[4];
    const float* beta  = (const float*)d_in[5];
    float* out = (float*)d_out;

    k_gemm  <<<dim3(OUTD / 64, N / 64), 256>>>(x, W);
    k_scores<<<(N * H) / 256, 256>>>(a);
    k_attn  <<<dim3(N / 32, 2), 256>>>(adj);
    k_zero  <<<1, 512>>>();
    k_combine<<<N / 32, 256>>>();
    k_norm  <<<(N * OUTD) / 256, 256>>>(gamma, beta, out);
}